// round 2
// baseline (speedup 1.0000x reference)
#include <cuda_runtime.h>
#include <cuda_fp16.h>
#include <cstdint>

#define BB 512
#define TT 128
#define II 512
#define HH 512
#define CCC 97
#define SS 26
#define GG 2048   // 4H
#define KX 1024   // I + H (gates GEMM K)
#define IC 609    // I + C (W_ih row length)

// ---------------- device scratch (no allocations allowed) ----------------
__device__ __half g_bh[BB * TT * II];          // batch_H cast fp16        67 MB
__device__ __half g_feat[BB * TT * HH];        // encoder projection fp16  67 MB
__device__ __half g_Wfeat[HH * II];
__device__ __half g_Whid[HH * HH];
__device__ __half g_Wcat[GG * KX];             // [W_ih[:, :I] | W_hh], rows permuted p=4j+g
__device__ __half g_Wgen[128 * HH];            // padded to 128 rows
__device__ float  g_biasg[GG];                 // b_ih + b_hh (original row order)
__device__ float  g_hp[BB * HH];
__device__ float  g_c[BB * HH];
__device__ __half g_x[2][BB * KX];             // [ctx | h], double buffered
__device__ __half g_outh[BB * SS * HH];

// ---------------- helpers ----------------
__device__ __forceinline__ float fast_tanh(float x) {
    float y;
    asm("tanh.approx.f32 %0, %1;" : "=f"(y) : "f"(x));
    return y;
}
__device__ __forceinline__ float sigmoidf_(float x) {
    return 1.0f / (1.0f + __expf(-x));
}
__device__ __forceinline__ void mma16816(float* c, uint32_t a0, uint32_t a1, uint32_t a2,
                                         uint32_t a3, uint32_t b0, uint32_t b1) {
    asm volatile(
        "mma.sync.aligned.m16n8k16.row.col.f32.f16.f16.f32 "
        "{%0,%1,%2,%3},{%4,%5,%6,%7},{%8,%9},{%0,%1,%2,%3};\n"
        : "+f"(c[0]), "+f"(c[1]), "+f"(c[2]), "+f"(c[3])
        : "r"(a0), "r"(a1), "r"(a2), "r"(a3), "r"(b0), "r"(b1));
}
__device__ __forceinline__ void ldsm_x4(uint32_t& r0, uint32_t& r1, uint32_t& r2, uint32_t& r3,
                                        const void* p) {
    uint32_t addr = (uint32_t)__cvta_generic_to_shared(p);
    asm volatile("ldmatrix.sync.aligned.m8n8.x4.shared.b16 {%0,%1,%2,%3},[%4];"
                 : "=r"(r0), "=r"(r1), "=r"(r2), "=r"(r3)
                 : "r"(addr));
}

// ---------------- prologue casts ----------------
__global__ void prep_kernel(const float* __restrict__ W_feat, const float* __restrict__ W_hid,
                            const float* __restrict__ W_ih, const float* __restrict__ W_hh,
                            const float* __restrict__ b_ih, const float* __restrict__ b_hh,
                            const float* __restrict__ W_gen) {
    const int stride = gridDim.x * blockDim.x;
    const int t0 = blockIdx.x * blockDim.x + threadIdx.x;
    for (int i = t0; i < HH * II; i += stride) g_Wfeat[i] = __float2half(W_feat[i]);
    for (int i = t0; i < HH * HH; i += stride) g_Whid[i] = __float2half(W_hid[i]);
    for (int i = t0; i < GG * KX; i += stride) {
        int p = i >> 10, k = i & 1023;
        int j = p >> 2, g = p & 3;
        int orig = g * HH + j;
        float v = (k < II) ? W_ih[(size_t)orig * IC + k] : W_hh[(size_t)orig * HH + (k - II)];
        g_Wcat[i] = __float2half(v);
    }
    for (int i = t0; i < GG; i += stride) g_biasg[i] = b_ih[i] + b_hh[i];
    for (int i = t0; i < 128 * HH; i += stride) {
        int n = i >> 9, k = i & 511;
        g_Wgen[i] = __float2half(n < CCC ? W_gen[n * HH + k] : 0.0f);
    }
    for (int i = t0; i < BB * HH; i += stride) {
        g_c[i] = 0.0f;
        g_x[0][(i >> 9) * KX + II + (i & 511)] = __float2half(0.0f);
    }
}

__global__ void cast_bh_kernel(const float* __restrict__ bh) {
    size_t n = (size_t)BB * TT * II;
    size_t stride = (size_t)gridDim.x * blockDim.x * 2;
    for (size_t i = ((size_t)blockIdx.x * blockDim.x + threadIdx.x) * 2; i < n; i += stride) {
        float2 v = *(const float2*)(bh + i);
        *(__half2*)(g_bh + i) = __floats2half2_rn(v.x, v.y);
    }
}

// ---------------- generic fp16 mma GEMM (C[m,n] = sum_k A[m,k]*B[n,k]) ----------------
// EPI 0: feat   (A=g_bh,        B=g_Wfeat, out half g_feat)
// EPI 1: hp     (A=g_x[buf]+I,  B=g_Whid,  out fp32 g_hp + b_hid)
// EPI 2: gates  (A=g_x[buf],    B=g_Wcat,  fused LSTM pointwise epilogue)
// EPI 3: logits (A=g_outh,      B=g_Wgen,  out fp32 d_out + b_gen, cols<97)
template <int EPI>
__global__ void __launch_bounds__(256)
gemm_kernel(int xbuf, float* __restrict__ outF, const float* __restrict__ bias,
            int step, int nxt, const float* __restrict__ W_ih, const int* __restrict__ text) {
    constexpr int BM = 64, BN = 128, BK = 64;
    constexpr int K = (EPI == 2) ? 1024 : 512;
    constexpr int SA = BM * (BK + 8) * 2;   // 9216
    constexpr int SB = BN * (BK + 8) * 2;   // 18432
    constexpr int SMEMB = (EPI == 2) ? (BM * BN * 4) : (SA + SB);  // Cs overlaps As/Bs
    __shared__ __align__(16) char sbuf[SMEMB];
    __half(*As)[BK + 8] = (__half(*)[BK + 8])sbuf;
    __half(*Bs)[BK + 8] = (__half(*)[BK + 8])(sbuf + SA);
    float* Cs = (float*)sbuf;

    const __half* A;
    const __half* Bm;
    int lda, ldb;
    if (EPI == 0)      { A = g_bh;              lda = II; Bm = g_Wfeat; ldb = II; }
    else if (EPI == 1) { A = g_x[xbuf] + II;    lda = KX; Bm = g_Whid;  ldb = HH; }
    else if (EPI == 2) { A = g_x[xbuf];         lda = KX; Bm = g_Wcat;  ldb = KX; }
    else               { A = g_outh;            lda = HH; Bm = g_Wgen;  ldb = HH; }

    const int tid = threadIdx.x;
    const int lane = tid & 31, wid = tid >> 5;
    const int wm = wid & 1, wn = wid >> 1;   // warps 2(M) x 4(N), each 32x32
    const int n0 = blockIdx.x * BN;
    const int m0 = blockIdx.y * BM;

    float acc[2][4][4];
#pragma unroll
    for (int a = 0; a < 2; a++)
#pragma unroll
        for (int b = 0; b < 4; b++)
#pragma unroll
            for (int c = 0; c < 4; c++) acc[a][b][c] = 0.0f;

    for (int k0 = 0; k0 < K; k0 += BK) {
#pragma unroll
        for (int p = 0; p < 2; p++) {
            int linear = p * 2048 + tid * 8;
            int r = linear >> 6, c = linear & 63;
            *(uint4*)&As[r][c] = *(const uint4*)(A + (size_t)(m0 + r) * lda + k0 + c);
        }
#pragma unroll
        for (int p = 0; p < 4; p++) {
            int linear = p * 2048 + tid * 8;
            int r = linear >> 6, c = linear & 63;
            *(uint4*)&Bs[r][c] = *(const uint4*)(Bm + (size_t)(n0 + r) * ldb + k0 + c);
        }
        __syncthreads();
#pragma unroll
        for (int ks = 0; ks < 4; ks++) {
            uint32_t a[2][4];
#pragma unroll
            for (int mt = 0; mt < 2; mt++) {
                int row = wm * 32 + mt * 16 + (lane & 15);
                int col = ks * 16 + (lane >> 4) * 8;
                ldsm_x4(a[mt][0], a[mt][1], a[mt][2], a[mt][3], &As[row][col]);
            }
            uint32_t b[4][2];
#pragma unroll
            for (int nt2 = 0; nt2 < 2; nt2++) {
                int row = wn * 32 + nt2 * 16 + (lane & 7) + (lane >> 4) * 8;
                int col = ks * 16 + ((lane >> 3) & 1) * 8;
                uint32_t r0, r1, r2, r3;
                ldsm_x4(r0, r1, r2, r3, &Bs[row][col]);
                b[nt2 * 2 + 0][0] = r0; b[nt2 * 2 + 0][1] = r1;
                b[nt2 * 2 + 1][0] = r2; b[nt2 * 2 + 1][1] = r3;
            }
#pragma unroll
            for (int mt = 0; mt < 2; mt++)
#pragma unroll
                for (int nt = 0; nt < 4; nt++)
                    mma16816(acc[mt][nt], a[mt][0], a[mt][1], a[mt][2], a[mt][3],
                             b[nt][0], b[nt][1]);
        }
        __syncthreads();
    }

    // ---------------- epilogues ----------------
#pragma unroll
    for (int mt = 0; mt < 2; mt++)
#pragma unroll
        for (int nt = 0; nt < 4; nt++) {
            int lr = wm * 32 + mt * 16 + (lane >> 2);
            int lc = wn * 32 + nt * 8 + (lane & 3) * 2;
            int row = m0 + lr;
            int col = n0 + lc;
            float* v = acc[mt][nt];
            if (EPI == 0) {
                *(__half2*)(g_feat + (size_t)row * HH + col) = __floats2half2_rn(v[0], v[1]);
                *(__half2*)(g_feat + (size_t)(row + 8) * HH + col) = __floats2half2_rn(v[2], v[3]);
            } else if (EPI == 1) {
                float2 o0 = {v[0] + bias[col], v[1] + bias[col + 1]};
                float2 o1 = {v[2] + bias[col], v[3] + bias[col + 1]};
                *(float2*)(g_hp + (size_t)row * HH + col) = o0;
                *(float2*)(g_hp + (size_t)(row + 8) * HH + col) = o1;
            } else if (EPI == 3) {
                if (col < CCC)     outF[(size_t)row * CCC + col] = v[0] + bias[col];
                if (col + 1 < CCC) outF[(size_t)row * CCC + col + 1] = v[1] + bias[col + 1];
                if (col < CCC)     outF[(size_t)(row + 8) * CCC + col] = v[2] + bias[col];
                if (col + 1 < CCC) outF[(size_t)(row + 8) * CCC + col + 1] = v[3] + bias[col + 1];
            } else {  // EPI == 2: spill to smem for pointwise
                Cs[lr * BN + lc] = v[0];
                Cs[lr * BN + lc + 1] = v[1];
                Cs[(lr + 8) * BN + lc] = v[2];
                Cs[(lr + 8) * BN + lc + 1] = v[3];
            }
        }

    if (EPI == 2) {
        __syncthreads();
        const int jj = lane;
        const int j = (n0 >> 2) + jj;  // this CTA owns hidden units [n0/4, n0/4+32)
#pragma unroll
        for (int pass = 0; pass < 8; pass++) {
            int bl = pass * 8 + wid;
            int b = m0 + bl;
            float4 gv = *(const float4*)&Cs[bl * BN + jj * 4];  // [i,f,g,o] for (b,j)
            int txt = text[b * SS + step];
            float xi = gv.x + g_biasg[0 * HH + j] + W_ih[(size_t)(0 * HH + j) * IC + II + txt];
            float xf = gv.y + g_biasg[1 * HH + j] + W_ih[(size_t)(1 * HH + j) * IC + II + txt];
            float xg = gv.z + g_biasg[2 * HH + j] + W_ih[(size_t)(2 * HH + j) * IC + II + txt];
            float xo = gv.w + g_biasg[3 * HH + j] + W_ih[(size_t)(3 * HH + j) * IC + II + txt];
            float iS = sigmoidf_(xi), fS = sigmoidf_(xf), oS = sigmoidf_(xo);
            float gT = tanhf(xg);
            float cP = g_c[b * HH + j];
            float c2 = fS * cP + iS * gT;
            float h2 = oS * tanhf(c2);
            g_c[b * HH + j] = c2;
            g_x[nxt][b * KX + II + j] = __float2half(h2);
            g_outh[((size_t)b * SS + step) * HH + j] = __float2half(h2);
        }
    }
}

// ---------------- fused attention: e-scores + softmax + context (CTA per b) ----------------
__global__ void __launch_bounds__(256) att_kernel(int xbuf, const float* __restrict__ w_score) {
    __shared__ float hp_s[HH];
    __shared__ float w_s[HH];
    __shared__ float e_s[TT];
    const int b = blockIdx.x;
    const int tid = threadIdx.x, lane = tid & 31, wid = tid >> 5;
    for (int i = tid; i < HH; i += 256) {
        hp_s[i] = g_hp[b * HH + i];
        w_s[i] = w_score[i];
    }
    __syncthreads();

    const __half* featb = g_feat + (size_t)b * TT * HH;
    for (int t = wid; t < TT; t += 8) {
        const __half* fr = featb + (size_t)t * HH;
        float acc = 0.0f;
#pragma unroll
        for (int q = 0; q < 8; q++) {
            int h = q * 64 + lane * 2;
            float2 f = __half22float2(*(const __half2*)(fr + h));
            acc += w_s[h] * fast_tanh(f.x + hp_s[h]);
            acc += w_s[h + 1] * fast_tanh(f.y + hp_s[h + 1]);
        }
#pragma unroll
        for (int o = 16; o; o >>= 1) acc += __shfl_xor_sync(0xffffffffu, acc, o);
        if (lane == 0) e_s[t] = acc;
    }
    __syncthreads();

    if (wid == 0) {
        float v[4];
        float m = -1e30f;
#pragma unroll
        for (int q = 0; q < 4; q++) { v[q] = e_s[lane + 32 * q]; m = fmaxf(m, v[q]); }
#pragma unroll
        for (int o = 16; o; o >>= 1) m = fmaxf(m, __shfl_xor_sync(0xffffffffu, m, o));
        float ssum = 0.0f;
#pragma unroll
        for (int q = 0; q < 4; q++) { v[q] = __expf(v[q] - m); ssum += v[q]; }
#pragma unroll
        for (int o = 16; o; o >>= 1) ssum += __shfl_xor_sync(0xffffffffu, ssum, o);
        float inv = 1.0f / ssum;
#pragma unroll
        for (int q = 0; q < 4; q++) e_s[lane + 32 * q] = v[q] * inv;
    }
    __syncthreads();

    const __half* bhb = g_bh + (size_t)b * TT * II;
    float ax = 0.0f, ay = 0.0f;
    const int i2 = tid * 2;
#pragma unroll 4
    for (int t = 0; t < TT; t++) {
        float a = e_s[t];
        float2 f = __half22float2(*(const __half2*)(bhb + (size_t)t * II + i2));
        ax += a * f.x;
        ay += a * f.y;
    }
    *(__half2*)(&g_x[xbuf][b * KX + i2]) = __floats2half2_rn(ax, ay);
}

// ---------------- launch ----------------
extern "C" void kernel_launch(void* const* d_in, const int* in_sizes, int n_in,
                              void* d_out, int out_size) {
    const float* batch_H = (const float*)d_in[0];
    const int* text = (const int*)d_in[1];
    const float* W_feat = (const float*)d_in[2];
    const float* W_hid = (const float*)d_in[3];
    const float* b_hid = (const float*)d_in[4];
    const float* w_score = (const float*)d_in[5];
    const float* W_ih = (const float*)d_in[6];
    const float* W_hh = (const float*)d_in[7];
    const float* b_ih = (const float*)d_in[8];
    const float* b_hh = (const float*)d_in[9];
    const float* W_gen = (const float*)d_in[10];
    const float* b_gen = (const float*)d_in[11];
    float* out = (float*)d_out;

    prep_kernel<<<1024, 256>>>(W_feat, W_hid, W_ih, W_hh, b_ih, b_hh, W_gen);
    cast_bh_kernel<<<8192, 256>>>(batch_H);
    // feat: M=B*T=65536, N=512, K=512
    gemm_kernel<0><<<dim3(4, 1024), 256>>>(0, nullptr, nullptr, 0, 0, nullptr, nullptr);

    for (int s = 0; s < SS; s++) {
        int cur = s & 1, nxt = cur ^ 1;
        // hp = h @ W_hid^T + b_hid : M=512, N=512
        gemm_kernel<1><<<dim3(4, 8), 256>>>(cur, nullptr, b_hid, 0, 0, nullptr, nullptr);
        // attention scores + softmax + context
        att_kernel<<<512, 256>>>(cur, w_score);
        // gates = [ctx|h] @ [W_ih|W_hh]^T (+onehot col, biases) then LSTM pointwise
        gemm_kernel<2><<<dim3(16, 8), 256>>>(cur, nullptr, nullptr, s, nxt, W_ih, text);
    }
    // probs = out_h @ W_gen^T + b_gen : M=B*S=13312, N=97(pad 128)
    gemm_kernel<3><<<dim3(1, 208), 256>>>(0, out, b_gen, 0, 0, nullptr, nullptr);
}

// round 4
// speedup vs baseline: 1.2214x; 1.2214x over previous
#include <cuda_runtime.h>
#include <cuda_fp16.h>
#include <cstdint>

#define BB 512
#define TT 128
#define II 512
#define HH 512
#define CCC 97
#define SS 26
#define GG 2048   // 4H
#define KX 1024   // I + H (gates GEMM K)
#define IC 609    // I + C (W_ih row length)

// ---------------- device scratch (no allocations allowed) ----------------
__device__ __half g_bh[BB * TT * II];          // batch_H cast fp16        67 MB
__device__ __half g_feat[BB * TT * HH];        // encoder projection fp16  67 MB
__device__ __half g_Wfeat[HH * II];
__device__ __half g_Whid[HH * HH];
__device__ __half g_Wcat[GG * KX];             // [W_ih[:, :I] | W_hh], rows permuted p=4j+g
__device__ __half g_Wgen[128 * HH];            // padded to 128 rows
__device__ float  g_biasg[GG];                 // b_ih + b_hh (original row order)
__device__ float  g_hp[BB * HH];
__device__ float  g_c[BB * HH];
__device__ __half g_x[2][BB * KX];             // [ctx | h], double buffered
__device__ __half g_outh[BB * SS * HH];

// ---------------- helpers ----------------
__device__ __forceinline__ float fast_tanh(float x) {
    float y;
    asm("tanh.approx.f32 %0, %1;" : "=f"(y) : "f"(x));
    return y;
}
__device__ __forceinline__ float sigmoidf_(float x) {
    return 1.0f / (1.0f + __expf(-x));
}
__device__ __forceinline__ void mma16816(float* c, uint32_t a0, uint32_t a1, uint32_t a2,
                                         uint32_t a3, uint32_t b0, uint32_t b1) {
    asm volatile(
        "mma.sync.aligned.m16n8k16.row.col.f32.f16.f16.f32 "
        "{%0,%1,%2,%3},{%4,%5,%6,%7},{%8,%9},{%0,%1,%2,%3};\n"
        : "+f"(c[0]), "+f"(c[1]), "+f"(c[2]), "+f"(c[3])
        : "r"(a0), "r"(a1), "r"(a2), "r"(a3), "r"(b0), "r"(b1));
}
__device__ __forceinline__ void ldsm_x4(uint32_t& r0, uint32_t& r1, uint32_t& r2, uint32_t& r3,
                                        const void* p) {
    uint32_t addr = (uint32_t)__cvta_generic_to_shared(p);
    asm volatile("ldmatrix.sync.aligned.m8n8.x4.shared.b16 {%0,%1,%2,%3},[%4];"
                 : "=r"(r0), "=r"(r1), "=r"(r2), "=r"(r3)
                 : "r"(addr));
}
__device__ __forceinline__ void cp_async16(void* smem, const void* gmem) {
    uint32_t s = (uint32_t)__cvta_generic_to_shared(smem);
    asm volatile("cp.async.cg.shared.global [%0], [%1], 16;\n" ::"r"(s), "l"(gmem));
}
__device__ __forceinline__ void cp_commit() { asm volatile("cp.async.commit_group;\n"); }
template <int N>
__device__ __forceinline__ void cp_wait() { asm volatile("cp.async.wait_group %0;\n" ::"n"(N)); }

// ---------------- prologue casts ----------------
__global__ void prep_kernel(const float* __restrict__ W_feat, const float* __restrict__ W_hid,
                            const float* __restrict__ W_ih, const float* __restrict__ W_hh,
                            const float* __restrict__ b_ih, const float* __restrict__ b_hh,
                            const float* __restrict__ W_gen) {
    const int stride = gridDim.x * blockDim.x;
    const int t0 = blockIdx.x * blockDim.x + threadIdx.x;
    for (int i = t0; i < HH * II; i += stride) g_Wfeat[i] = __float2half(W_feat[i]);
    for (int i = t0; i < HH * HH; i += stride) g_Whid[i] = __float2half(W_hid[i]);
    for (int i = t0; i < GG * KX; i += stride) {
        int p = i >> 10, k = i & 1023;
        int j = p >> 2, g = p & 3;
        int orig = g * HH + j;
        float v = (k < II) ? W_ih[(size_t)orig * IC + k] : W_hh[(size_t)orig * HH + (k - II)];
        g_Wcat[i] = __float2half(v);
    }
    for (int i = t0; i < GG; i += stride) g_biasg[i] = b_ih[i] + b_hh[i];
    for (int i = t0; i < 128 * HH; i += stride) {
        int n = i >> 9, k = i & 511;
        g_Wgen[i] = __float2half(n < CCC ? W_gen[n * HH + k] : 0.0f);
    }
    for (int i = t0; i < BB * HH; i += stride) {
        g_c[i] = 0.0f;
        g_x[0][(i >> 9) * KX + II + (i & 511)] = __float2half(0.0f);
    }
}

__global__ void cast_bh_kernel(const float* __restrict__ bh) {
    size_t n = (size_t)BB * TT * II;
    size_t stride = (size_t)gridDim.x * blockDim.x * 2;
    for (size_t i = ((size_t)blockIdx.x * blockDim.x + threadIdx.x) * 2; i < n; i += stride) {
        float2 v = *(const float2*)(bh + i);
        *(__half2*)(g_bh + i) = __floats2half2_rn(v.x, v.y);
    }
}

// ---------------- generic fp16 mma GEMM, 3-stage cp.async pipeline ----------------
// C[m,n] = sum_k A[m,k]*B[n,k]
// EPI 0: feat   (A=g_bh,        B=g_Wfeat, out half g_feat)
// EPI 1: hp     (A=g_x[buf]+I,  B=g_Whid,  out fp32 g_hp + b_hid)
// EPI 2: gates  (A=g_x[buf],    B=g_Wcat,  fused LSTM pointwise epilogue)
// EPI 3: logits (A=g_outh,      B=g_Wgen,  out fp32 d_out + b_gen, cols<97)
template <int EPI>
__global__ void __launch_bounds__(256)
gemm_kernel(int xbuf, float* __restrict__ outF, const float* __restrict__ bias,
            int step, int nxt, const float* __restrict__ W_ih, const int* __restrict__ text) {
    constexpr int BM = 64, BN = 128, BK = 32;
    constexpr int K = (EPI == 2) ? 1024 : 512;
    constexpr int nK = K / BK;
    constexpr int LDS_ = BK + 8;             // 40 halves -> 80B rows (16B multiple)
    constexpr int SA = BM * LDS_ * 2;        // 5120
    constexpr int SB = BN * LDS_ * 2;        // 10240
    constexpr int STG = SA + SB;             // 15360
    constexpr int CS_BYTES = BM * BN * 4;    // 32768 (EPI2 epilogue)
    constexpr int SMEMB = (EPI == 2) ? (3 * STG > CS_BYTES ? 3 * STG : CS_BYTES) : 3 * STG;
    __shared__ __align__(16) char sbuf[SMEMB];
    float* Cs = (float*)sbuf;

    const __half* A;
    const __half* Bm;
    int lda, ldb;
    if (EPI == 0)      { A = g_bh;           lda = II; Bm = g_Wfeat; ldb = II; }
    else if (EPI == 1) { A = g_x[xbuf] + II; lda = KX; Bm = g_Whid;  ldb = HH; }
    else if (EPI == 2) { A = g_x[xbuf];      lda = KX; Bm = g_Wcat;  ldb = KX; }
    else               { A = g_outh;         lda = HH; Bm = g_Wgen;  ldb = HH; }

    const int tid = threadIdx.x;
    const int lane = tid & 31, wid = tid >> 5;
    const int wm = wid & 1, wn = wid >> 1;   // warps 2(M) x 4(N), each 32x32
    const int n0 = blockIdx.x * BN;
    const int m0 = blockIdx.y * BM;

    // per-thread load coords (16B granules)
    const int ar = tid >> 2, ac = (tid & 3) * 8;          // A: 64x32, one pass
    const int br0 = tid >> 2, bc = (tid & 3) * 8;         // B: 128x32, two passes

    auto As = [&](int s) { return (__half(*)[LDS_])(sbuf + s * STG); };
    auto Bs = [&](int s) { return (__half(*)[LDS_])(sbuf + s * STG + SA); };

    auto load_tiles = [&](int kb, int s) {
        const int k0 = kb * BK;
        cp_async16(&As(s)[ar][ac], A + (size_t)(m0 + ar) * lda + k0 + ac);
        cp_async16(&Bs(s)[br0][bc], Bm + (size_t)(n0 + br0) * ldb + k0 + bc);
        cp_async16(&Bs(s)[br0 + 64][bc], Bm + (size_t)(n0 + br0 + 64) * ldb + k0 + bc);
        cp_commit();
    };

    float acc[2][4][4];
#pragma unroll
    for (int a = 0; a < 2; a++)
#pragma unroll
        for (int b = 0; b < 4; b++)
#pragma unroll
            for (int c = 0; c < 4; c++) acc[a][b][c] = 0.0f;

    load_tiles(0, 0);
    load_tiles(1, 1);

    for (int kb = 0; kb < nK; kb++) {
        if (kb < nK - 1) cp_wait<1>(); else cp_wait<0>();
        __syncthreads();
        if (kb + 2 < nK) load_tiles(kb + 2, (kb + 2) % 3);
        const int cur = kb % 3;
        __half(*Asc)[LDS_] = As(cur);
        __half(*Bsc)[LDS_] = Bs(cur);
#pragma unroll
        for (int ks = 0; ks < 2; ks++) {
            uint32_t a[2][4];
#pragma unroll
            for (int mt = 0; mt < 2; mt++) {
                int row = wm * 32 + mt * 16 + (lane & 15);
                int col = ks * 16 + (lane >> 4) * 8;
                ldsm_x4(a[mt][0], a[mt][1], a[mt][2], a[mt][3], &Asc[row][col]);
            }
            uint32_t b[4][2];
#pragma unroll
            for (int nt2 = 0; nt2 < 2; nt2++) {
                int row = wn * 32 + nt2 * 16 + (lane & 7) + (lane >> 4) * 8;
                int col = ks * 16 + ((lane >> 3) & 1) * 8;
                uint32_t r0, r1, r2, r3;
                ldsm_x4(r0, r1, r2, r3, &Bsc[row][col]);
                b[nt2 * 2 + 0][0] = r0; b[nt2 * 2 + 0][1] = r1;
                b[nt2 * 2 + 1][0] = r2; b[nt2 * 2 + 1][1] = r3;
            }
#pragma unroll
            for (int mt = 0; mt < 2; mt++)
#pragma unroll
                for (int nt = 0; nt < 4; nt++)
                    mma16816(acc[mt][nt], a[mt][0], a[mt][1], a[mt][2], a[mt][3],
                             b[nt][0], b[nt][1]);
        }
        __syncthreads();
    }

    // ---------------- epilogues ----------------
#pragma unroll
    for (int mt = 0; mt < 2; mt++)
#pragma unroll
        for (int nt = 0; nt < 4; nt++) {
            int lr = wm * 32 + mt * 16 + (lane >> 2);
            int lc = wn * 32 + nt * 8 + (lane & 3) * 2;
            int row = m0 + lr;
            int col = n0 + lc;
            float* v = acc[mt][nt];
            if (EPI == 0) {
                *(__half2*)(g_feat + (size_t)row * HH + col) = __floats2half2_rn(v[0], v[1]);
                *(__half2*)(g_feat + (size_t)(row + 8) * HH + col) = __floats2half2_rn(v[2], v[3]);
            } else if (EPI == 1) {
                float2 o0 = {v[0] + bias[col], v[1] + bias[col + 1]};
                float2 o1 = {v[2] + bias[col], v[3] + bias[col + 1]};
                *(float2*)(g_hp + (size_t)row * HH + col) = o0;
                *(float2*)(g_hp + (size_t)(row + 8) * HH + col) = o1;
            } else if (EPI == 3) {
                if (col < CCC)     outF[(size_t)row * CCC + col] = v[0] + bias[col];
                if (col + 1 < CCC) outF[(size_t)row * CCC + col + 1] = v[1] + bias[col + 1];
                if (col < CCC)     outF[(size_t)(row + 8) * CCC + col] = v[2] + bias[col];
                if (col + 1 < CCC) outF[(size_t)(row + 8) * CCC + col + 1] = v[3] + bias[col + 1];
            } else {  // EPI == 2: spill to smem for pointwise
                Cs[lr * BN + lc] = v[0];
                Cs[lr * BN + lc + 1] = v[1];
                Cs[(lr + 8) * BN + lc] = v[2];
                Cs[(lr + 8) * BN + lc + 1] = v[3];
            }
        }

    if (EPI == 2) {
        __syncthreads();
        const int jj = lane;
        const int j = (n0 >> 2) + jj;  // this CTA owns hidden units [n0/4, n0/4+32)
#pragma unroll
        for (int pass = 0; pass < 8; pass++) {
            int bl = pass * 8 + wid;
            int b = m0 + bl;
            float4 gv = *(const float4*)&Cs[bl * BN + jj * 4];  // [i,f,g,o] for (b,j)
            int txt = text[b * SS + step];
            float xi = gv.x + g_biasg[0 * HH + j] + W_ih[(size_t)(0 * HH + j) * IC + II + txt];
            float xf = gv.y + g_biasg[1 * HH + j] + W_ih[(size_t)(1 * HH + j) * IC + II + txt];
            float xg = gv.z + g_biasg[2 * HH + j] + W_ih[(size_t)(2 * HH + j) * IC + II + txt];
            float xo = gv.w + g_biasg[3 * HH + j] + W_ih[(size_t)(3 * HH + j) * IC + II + txt];
            float iS = sigmoidf_(xi), fS = sigmoidf_(xf), oS = sigmoidf_(xo);
            float gT = tanhf(xg);
            float cP = g_c[b * HH + j];
            float c2 = fS * cP + iS * gT;
            float h2 = oS * tanhf(c2);
            g_c[b * HH + j] = c2;
            g_x[nxt][b * KX + II + j] = __float2half(h2);
            g_outh[((size_t)b * SS + step) * HH + j] = __float2half(h2);
        }
    }
}

// ---------------- fused attention: e-scores + softmax + context (CTA per b) ----------------
__global__ void __launch_bounds__(256) att_kernel(int xbuf, const float* __restrict__ w_score) {
    __shared__ float hp_s[HH];
    __shared__ float w_s[HH];
    __shared__ float e_s[TT];
    const int b = blockIdx.x;
    const int tid = threadIdx.x, lane = tid & 31, wid = tid >> 5;
    for (int i = tid; i < HH; i += 256) {
        hp_s[i] = g_hp[b * HH + i];
        w_s[i] = w_score[i];
    }
    __syncthreads();

    const __half* featb = g_feat + (size_t)b * TT * HH;
    for (int t = wid; t < TT; t += 8) {
        const __half* fr = featb + (size_t)t * HH;
        float acc = 0.0f;
#pragma unroll
        for (int q = 0; q < 8; q++) {
            int h = q * 64 + lane * 2;
            float2 f = __half22float2(*(const __half2*)(fr + h));
            acc += w_s[h] * fast_tanh(f.x + hp_s[h]);
            acc += w_s[h + 1] * fast_tanh(f.y + hp_s[h + 1]);
        }
#pragma unroll
        for (int o = 16; o; o >>= 1) acc += __shfl_xor_sync(0xffffffffu, acc, o);
        if (lane == 0) e_s[t] = acc;
    }
    __syncthreads();

    if (wid == 0) {
        float v[4];
        float m = -1e30f;
#pragma unroll
        for (int q = 0; q < 4; q++) { v[q] = e_s[lane + 32 * q]; m = fmaxf(m, v[q]); }
#pragma unroll
        for (int o = 16; o; o >>= 1) m = fmaxf(m, __shfl_xor_sync(0xffffffffu, m, o));
        float ssum = 0.0f;
#pragma unroll
        for (int q = 0; q < 4; q++) { v[q] = __expf(v[q] - m); ssum += v[q]; }
#pragma unroll
        for (int o = 16; o; o >>= 1) ssum += __shfl_xor_sync(0xffffffffu, ssum, o);
        float inv = 1.0f / ssum;
#pragma unroll
        for (int q = 0; q < 4; q++) e_s[lane + 32 * q] = v[q] * inv;
    }
    __syncthreads();

    const __half* bhb = g_bh + (size_t)b * TT * II;
    float ax = 0.0f, ay = 0.0f;
    const int i2 = tid * 2;
#pragma unroll 8
    for (int t = 0; t < TT; t++) {
        float a = e_s[t];
        float2 f = __half22float2(*(const __half2*)(bhb + (size_t)t * II + i2));
        ax += a * f.x;
        ay += a * f.y;
    }
    *(__half2*)(&g_x[xbuf][b * KX + i2]) = __floats2half2_rn(ax, ay);
}

// ---------------- launch ----------------
extern "C" void kernel_launch(void* const* d_in, const int* in_sizes, int n_in,
                              void* d_out, int out_size) {
    const float* batch_H = (const float*)d_in[0];
    const int* text = (const int*)d_in[1];
    const float* W_feat = (const float*)d_in[2];
    const float* W_hid = (const float*)d_in[3];
    const float* b_hid = (const float*)d_in[4];
    const float* w_score = (const float*)d_in[5];
    const float* W_ih = (const float*)d_in[6];
    const float* W_hh = (const float*)d_in[7];
    const float* b_ih = (const float*)d_in[8];
    const float* b_hh = (const float*)d_in[9];
    const float* W_gen = (const float*)d_in[10];
    const float* b_gen = (const float*)d_in[11];
    float* out = (float*)d_out;

    prep_kernel<<<1024, 256>>>(W_feat, W_hid, W_ih, W_hh, b_ih, b_hh, W_gen);
    cast_bh_kernel<<<8192, 256>>>(batch_H);
    // feat: M=B*T=65536, N=512, K=512
    gemm_kernel<0><<<dim3(4, 1024), 256>>>(0, nullptr, nullptr, 0, 0, nullptr, nullptr);

    for (int s = 0; s < SS; s++) {
        int cur = s & 1, nxt = cur ^ 1;
        // hp = h @ W_hid^T + b_hid : M=512, N=512
        gemm_kernel<1><<<dim3(4, 8), 256>>>(cur, nullptr, b_hid, 0, 0, nullptr, nullptr);
        // attention scores + softmax + context
        att_kernel<<<512, 256>>>(cur, w_score);
        // gates = [ctx|h] @ [W_ih|W_hh]^T (+onehot col, biases) then LSTM pointwise
        gemm_kernel<2><<<dim3(16, 8), 256>>>(cur, nullptr, nullptr, s, nxt, W_ih, text);
    }
    // probs = out_h @ W_gen^T + b_gen : M=B*S=13312, N=97(pad 128)
    gemm_kernel<3><<<dim3(1, 208), 256>>>(0, out, b_gen, 0, 0, nullptr, nullptr);
}

// round 9
// speedup vs baseline: 1.3144x; 1.0762x over previous
#include <cuda_runtime.h>
#include <cuda_fp16.h>
#include <cstdint>

#define BB 512
#define TT 128
#define II 512
#define HH 512
#define CCC 97
#define SS 26
#define GG 2048   // 4H
#define KX 1024   // g_x row: [ctx(512) | h(512)]
#define IC 609    // I + C (W_ih row length)

// ---------------- device scratch (no allocations allowed) ----------------
__device__ __half g_bh[BB * TT * II];          // batch_H cast fp16        67 MB
__device__ __half g_feat[BB * TT * HH];        // encoder projection fp16  67 MB
__device__ __half g_Wfeat[HH * II];
__device__ __half g_Whid[HH * HH];
__device__ __half g_Wih_p[GG * II];            // W_ih[:, :I], rows permuted p=4j+g
__device__ __half g_Whh_p[GG * HH];            // W_hh, rows permuted p=4j+g
__device__ __half g_Wgen[128 * HH];            // padded to 128 rows
__device__ float  g_biasg[GG];                 // b_ih + b_hh (original row order)
__device__ float  g_hp[BB * HH];
__device__ float  g_c[BB * HH];
__device__ __half g_gh[BB * GG];               // h @ W_hh^T (permuted cols), fp16
__device__ __half g_x[2][BB * KX];             // [ctx | h], double buffered
__device__ __half g_outh[BB * SS * HH];

// ---------------- tile constants ----------------
constexpr int BM = 64, BN = 128, BK = 32;
constexpr int GK = 512;                  // all GEMMs K=512 now
constexpr int nK = GK / BK;              // 16
constexpr int LDS_ = BK + 8;             // 40 halves
constexpr int SA = BM * LDS_ * 2;        // 5120
constexpr int SB = BN * LDS_ * 2;        // 10240
constexpr int STG = SA + SB;             // 15360
constexpr int SMEMB = 3 * STG;           // 46080 (>= Cs 32768)

// ---------------- helpers ----------------
__device__ __forceinline__ float fast_tanh(float x) {
    float y;
    asm("tanh.approx.f32 %0, %1;" : "=f"(y) : "f"(x));
    return y;
}
__device__ __forceinline__ float sigmoidf_(float x) {
    return 1.0f / (1.0f + __expf(-x));
}
__device__ __forceinline__ void mma16816(float* c, uint32_t a0, uint32_t a1, uint32_t a2,
                                         uint32_t a3, uint32_t b0, uint32_t b1) {
    asm volatile(
        "mma.sync.aligned.m16n8k16.row.col.f32.f16.f16.f32 "
        "{%0,%1,%2,%3},{%4,%5,%6,%7},{%8,%9},{%0,%1,%2,%3};\n"
        : "+f"(c[0]), "+f"(c[1]), "+f"(c[2]), "+f"(c[3])
        : "r"(a0), "r"(a1), "r"(a2), "r"(a3), "r"(b0), "r"(b1));
}
__device__ __forceinline__ void ldsm_x4(uint32_t& r0, uint32_t& r1, uint32_t& r2, uint32_t& r3,
                                        const void* p) {
    uint32_t addr = (uint32_t)__cvta_generic_to_shared(p);
    asm volatile("ldmatrix.sync.aligned.m8n8.x4.shared.b16 {%0,%1,%2,%3},[%4];"
                 : "=r"(r0), "=r"(r1), "=r"(r2), "=r"(r3)
                 : "r"(addr));
}
__device__ __forceinline__ void cp_async16(void* smem, const void* gmem) {
    uint32_t s = (uint32_t)__cvta_generic_to_shared(smem);
    asm volatile("cp.async.cg.shared.global [%0], [%1], 16;\n" ::"r"(s), "l"(gmem));
}
__device__ __forceinline__ void cp_commit() { asm volatile("cp.async.commit_group;\n"); }
template <int N>
__device__ __forceinline__ void cp_wait() { asm volatile("cp.async.wait_group %0;\n" ::"n"(N)); }

// ---------------- prologue casts ----------------
__global__ void prep_kernel(const float* __restrict__ W_feat, const float* __restrict__ W_hid,
                            const float* __restrict__ W_ih, const float* __restrict__ W_hh,
                            const float* __restrict__ b_ih, const float* __restrict__ b_hh,
                            const float* __restrict__ W_gen) {
    const int stride = gridDim.x * blockDim.x;
    const int t0 = blockIdx.x * blockDim.x + threadIdx.x;
    for (int i = t0; i < HH * II; i += stride) g_Wfeat[i] = __float2half(W_feat[i]);
    for (int i = t0; i < HH * HH; i += stride) g_Whid[i] = __float2half(W_hid[i]);
    for (int i = t0; i < GG * II; i += stride) {
        int p = i >> 9, k = i & 511;
        int j = p >> 2, g = p & 3;
        int orig = g * HH + j;
        g_Wih_p[i] = __float2half(W_ih[(size_t)orig * IC + k]);
        g_Whh_p[i] = __float2half(W_hh[(size_t)orig * HH + k]);
    }
    for (int i = t0; i < GG; i += stride) g_biasg[i] = b_ih[i] + b_hh[i];
    for (int i = t0; i < 128 * HH; i += stride) {
        int n = i >> 9, k = i & 511;
        g_Wgen[i] = __float2half(n < CCC ? W_gen[n * HH + k] : 0.0f);
    }
    for (int i = t0; i < BB * HH; i += stride) {
        g_c[i] = 0.0f;
        g_x[0][(i >> 9) * KX + II + (i & 511)] = __float2half(0.0f);
    }
}

__global__ void cast_bh_kernel(const float* __restrict__ bh) {
    size_t n = (size_t)BB * TT * II;
    size_t stride = (size_t)gridDim.x * blockDim.x * 2;
    for (size_t i = ((size_t)blockIdx.x * blockDim.x + threadIdx.x) * 2; i < n; i += stride) {
        float2 v = *(const float2*)(bh + i);
        *(__half2*)(g_bh + i) = __floats2half2_rn(v.x, v.y);
    }
}

// ---------------- generic fp16 mma GEMM body, 3-stage cp.async pipeline ----------------
// C[m,n] = sum_k A[m,k]*B[n,k], K = 512
// EPI 0: feat   (A=g_bh,       B=g_Wfeat,  out half g_feat)
// EPI 1: hp     (A=g_x[buf]+I, B=g_Whid,   out fp32 g_hp + b_hid)
// EPI 2: gates  (A=g_x[buf],   B=g_Wih_p,  epilogue: +gh +bias +onehot, LSTM pointwise)
// EPI 3: logits (A=g_outh,     B=g_Wgen,   out fp32 d_out + b_gen, cols<97)
// EPI 4: gh     (A=g_x[buf]+I, B=g_Whh_p,  out half g_gh)
template <int EPI>
__device__ __forceinline__ void
gemm_body(char* sbuf, int bx, int by, int xbuf, float* __restrict__ outF,
          const float* __restrict__ bias, int step, int nxt,
          const float* __restrict__ W_ih, const int* __restrict__ text) {
    float* Cs = (float*)sbuf;

    const __half* A;
    const __half* Bm;
    int lda, ldb;
    if (EPI == 0)      { A = g_bh;           lda = II; Bm = g_Wfeat; ldb = II; }
    else if (EPI == 1) { A = g_x[xbuf] + II; lda = KX; Bm = g_Whid;  ldb = HH; }
    else if (EPI == 2) { A = g_x[xbuf];      lda = KX; Bm = g_Wih_p; ldb = II; }
    else if (EPI == 3) { A = g_outh;         lda = HH; Bm = g_Wgen;  ldb = HH; }
    else               { A = g_x[xbuf] + II; lda = KX; Bm = g_Whh_p; ldb = II; }

    const int tid = threadIdx.x;
    const int lane = tid & 31, wid = tid >> 5;
    const int wm = wid & 1, wn = wid >> 1;   // warps 2(M) x 4(N), each 32x32
    const int n0 = bx * BN;
    const int m0 = by * BM;

    const int ar = tid >> 2, ac = (tid & 3) * 8;
    const int br0 = tid >> 2, bc = (tid & 3) * 8;

    auto As = [&](int s) { return (__half(*)[LDS_])(sbuf + s * STG); };
    auto Bs = [&](int s) { return (__half(*)[LDS_])(sbuf + s * STG + SA); };

    auto load_tiles = [&](int kb, int s) {
        const int k0 = kb * BK;
        cp_async16(&As(s)[ar][ac], A + (size_t)(m0 + ar) * lda + k0 + ac);
        cp_async16(&Bs(s)[br0][bc], Bm + (size_t)(n0 + br0) * ldb + k0 + bc);
        cp_async16(&Bs(s)[br0 + 64][bc], Bm + (size_t)(n0 + br0 + 64) * ldb + k0 + bc);
        cp_commit();
    };

    float acc[2][4][4];
#pragma unroll
    for (int a = 0; a < 2; a++)
#pragma unroll
        for (int b = 0; b < 4; b++)
#pragma unroll
            for (int c = 0; c < 4; c++) acc[a][b][c] = 0.0f;

    load_tiles(0, 0);
    load_tiles(1, 1);

    for (int kb = 0; kb < nK; kb++) {
        if (kb < nK - 1) cp_wait<1>(); else cp_wait<0>();
        __syncthreads();
        if (kb + 2 < nK) load_tiles(kb + 2, (kb + 2) % 3);
        const int cur = kb % 3;
        __half(*Asc)[LDS_] = As(cur);
        __half(*Bsc)[LDS_] = Bs(cur);
#pragma unroll
        for (int ks = 0; ks < 2; ks++) {
            uint32_t a[2][4];
#pragma unroll
            for (int mt = 0; mt < 2; mt++) {
                int row = wm * 32 + mt * 16 + (lane & 15);
                int col = ks * 16 + (lane >> 4) * 8;
                ldsm_x4(a[mt][0], a[mt][1], a[mt][2], a[mt][3], &Asc[row][col]);
            }
            uint32_t b[4][2];
#pragma unroll
            for (int nt2 = 0; nt2 < 2; nt2++) {
                int row = wn * 32 + nt2 * 16 + (lane & 7) + (lane >> 4) * 8;
                int col = ks * 16 + ((lane >> 3) & 1) * 8;
                uint32_t r0, r1, r2, r3;
                ldsm_x4(r0, r1, r2, r3, &Bsc[row][col]);
                b[nt2 * 2 + 0][0] = r0; b[nt2 * 2 + 0][1] = r1;
                b[nt2 * 2 + 1][0] = r2; b[nt2 * 2 + 1][1] = r3;
            }
#pragma unroll
            for (int mt = 0; mt < 2; mt++)
#pragma unroll
                for (int nt = 0; nt < 4; nt++)
                    mma16816(acc[mt][nt], a[mt][0], a[mt][1], a[mt][2], a[mt][3],
                             b[nt][0], b[nt][1]);
        }
        __syncthreads();
    }

    // ---------------- epilogues ----------------
#pragma unroll
    for (int mt = 0; mt < 2; mt++)
#pragma unroll
        for (int nt = 0; nt < 4; nt++) {
            int lr = wm * 32 + mt * 16 + (lane >> 2);
            int lc = wn * 32 + nt * 8 + (lane & 3) * 2;
            int row = m0 + lr;
            int col = n0 + lc;
            float* v = acc[mt][nt];
            if (EPI == 0) {
                *(__half2*)(g_feat + (size_t)row * HH + col) = __floats2half2_rn(v[0], v[1]);
                *(__half2*)(g_feat + (size_t)(row + 8) * HH + col) = __floats2half2_rn(v[2], v[3]);
            } else if (EPI == 1) {
                float2 o0 = {v[0] + bias[col], v[1] + bias[col + 1]};
                float2 o1 = {v[2] + bias[col], v[3] + bias[col + 1]};
                *(float2*)(g_hp + (size_t)row * HH + col) = o0;
                *(float2*)(g_hp + (size_t)(row + 8) * HH + col) = o1;
            } else if (EPI == 3) {
                if (col < CCC)     outF[(size_t)row * CCC + col] = v[0] + bias[col];
                if (col + 1 < CCC) outF[(size_t)row * CCC + col + 1] = v[1] + bias[col + 1];
                if (col < CCC)     outF[(size_t)(row + 8) * CCC + col] = v[2] + bias[col];
                if (col + 1 < CCC) outF[(size_t)(row + 8) * CCC + col + 1] = v[3] + bias[col + 1];
            } else if (EPI == 4) {
                *(__half2*)(g_gh + (size_t)row * GG + col) = __floats2half2_rn(v[0], v[1]);
                *(__half2*)(g_gh + (size_t)(row + 8) * GG + col) = __floats2half2_rn(v[2], v[3]);
            } else {  // EPI == 2: spill to smem for pointwise
                Cs[lr * BN + lc] = v[0];
                Cs[lr * BN + lc + 1] = v[1];
                Cs[(lr + 8) * BN + lc] = v[2];
                Cs[(lr + 8) * BN + lc + 1] = v[3];
            }
        }

    if (EPI == 2) {
        __syncthreads();
        const int jj = lane;
        const int j = (n0 >> 2) + jj;  // this CTA owns hidden units [n0/4, n0/4+32)
#pragma unroll
        for (int pass = 0; pass < 8; pass++) {
            int bl = pass * 8 + wid;
            int b = m0 + bl;
            float4 gv = *(const float4*)&Cs[bl * BN + jj * 4];  // ctx-part [i,f,g,o] for (b,j)
            // add h-part from g_gh (cols 4j..4j+3, permuted layout)
            __half2 gh01 = *(const __half2*)(g_gh + (size_t)b * GG + 4 * j);
            __half2 gh23 = *(const __half2*)(g_gh + (size_t)b * GG + 4 * j + 2);
            float2 g01 = __half22float2(gh01), g23 = __half22float2(gh23);
            int txt = text[b * SS + step];
            float xi = gv.x + g01.x + g_biasg[0 * HH + j] + W_ih[(size_t)(0 * HH + j) * IC + II + txt];
            float xf = gv.y + g01.y + g_biasg[1 * HH + j] + W_ih[(size_t)(1 * HH + j) * IC + II + txt];
            float xg = gv.z + g23.x + g_biasg[2 * HH + j] + W_ih[(size_t)(2 * HH + j) * IC + II + txt];
            float xo = gv.w + g23.y + g_biasg[3 * HH + j] + W_ih[(size_t)(3 * HH + j) * IC + II + txt];
            float iS = sigmoidf_(xi), fS = sigmoidf_(xf), oS = sigmoidf_(xo);
            float gT = tanhf(xg);
            float cP = g_c[b * HH + j];
            float c2 = fS * cP + iS * gT;
            float h2 = oS * tanhf(c2);
            g_c[b * HH + j] = c2;
            g_x[nxt][b * KX + II + j] = __float2half(h2);
            g_outh[((size_t)b * SS + step) * HH + j] = __float2half(h2);
        }
    }
}

template <int EPI>
__global__ void __launch_bounds__(256)
gemm_kernel(int xbuf, float* __restrict__ outF, const float* __restrict__ bias,
            int step, int nxt, const float* __restrict__ W_ih, const int* __restrict__ text) {
    __shared__ __align__(16) char sbuf[SMEMB];
    gemm_body<EPI>(sbuf, blockIdx.x, blockIdx.y, xbuf, outF, bias, step, nxt, W_ih, text);
}

// ---------------- fused: attention CTAs (blockIdx<BB) + gh-GEMM CTAs ----------------
__global__ void __launch_bounds__(256) att_gh_kernel(int xbuf, const float* __restrict__ w_score) {
    __shared__ __align__(16) char sbuf[SMEMB];
    if (blockIdx.x >= BB) {
        int lin = blockIdx.x - BB;  // 0..127 : gh GEMM M=512,N=2048
        gemm_body<4>(sbuf, lin & 15, lin >> 4, xbuf, nullptr, nullptr, 0, 0, nullptr, nullptr);
        return;
    }
    float* hp_s = (float*)sbuf;                 // 512 f
    float* w_s = (float*)(sbuf + 2048);         // 512 f
    float* e_s = (float*)(sbuf + 4096);         // 128 f
    const int b = blockIdx.x;
    const int tid = threadIdx.x, lane = tid & 31, wid = tid >> 5;
    for (int i = tid; i < HH; i += 256) {
        hp_s[i] = g_hp[b * HH + i];
        w_s[i] = w_score[i];
    }
    __syncthreads();

    const __half* featb = g_feat + (size_t)b * TT * HH;
    for (int t = wid; t < TT; t += 8) {
        const __half* fr = featb + (size_t)t * HH;
        float acc = 0.0f;
#pragma unroll
        for (int q = 0; q < 2; q++) {
            int h = q * 256 + lane * 8;
            uint4 fv = *(const uint4*)(fr + h);
            const __half2* fh = (const __half2*)&fv;
#pragma unroll
            for (int u = 0; u < 4; u++) {
                float2 f = __half22float2(fh[u]);
                acc += w_s[h + 2 * u] * fast_tanh(f.x + hp_s[h + 2 * u]);
                acc += w_s[h + 2 * u + 1] * fast_tanh(f.y + hp_s[h + 2 * u + 1]);
            }
        }
#pragma unroll
        for (int o = 16; o; o >>= 1) acc += __shfl_xor_sync(0xffffffffu, acc, o);
        if (lane == 0) e_s[t] = acc;
    }
    __syncthreads();

    if (wid == 0) {
        float v[4];
        float m = -1e30f;
#pragma unroll
        for (int q = 0; q < 4; q++) { v[q] = e_s[lane + 32 * q]; m = fmaxf(m, v[q]); }
#pragma unroll
        for (int o = 16; o; o >>= 1) m = fmaxf(m, __shfl_xor_sync(0xffffffffu, m, o));
        float ssum = 0.0f;
#pragma unroll
        for (int q = 0; q < 4; q++) { v[q] = __expf(v[q] - m); ssum += v[q]; }
#pragma unroll
        for (int o = 16; o; o >>= 1) ssum += __shfl_xor_sync(0xffffffffu, ssum, o);
        float inv = 1.0f / ssum;
#pragma unroll
        for (int q = 0; q < 4; q++) e_s[lane + 32 * q] = v[q] * inv;
    }
    __syncthreads();

    const __half* bhb = g_bh + (size_t)b * TT * II;
    float ax = 0.0f, ay = 0.0f;
    const int i2 = tid * 2;
#pragma unroll 8
    for (int t = 0; t < TT; t++) {
        float a = e_s[t];
        float2 f = __half22float2(*(const __half2*)(bhb + (size_t)t * II + i2));
        ax += a * f.x;
        ay += a * f.y;
    }
    *(__half2*)(&g_x[xbuf][b * KX + i2]) = __floats2half2_rn(ax, ay);
}

// ---------------- launch ----------------
extern "C" void kernel_launch(void* const* d_in, const int* in_sizes, int n_in,
                              void* d_out, int out_size) {
    const float* batch_H = (const float*)d_in[0];
    const int* text = (const int*)d_in[1];
    const float* W_feat = (const float*)d_in[2];
    const float* W_hid = (const float*)d_in[3];
    const float* b_hid = (const float*)d_in[4];
    const float* w_score = (const float*)d_in[5];
    const float* W_ih = (const float*)d_in[6];
    const float* W_hh = (const float*)d_in[7];
    const float* b_ih = (const float*)d_in[8];
    const float* b_hh = (const float*)d_in[9];
    const float* W_gen = (const float*)d_in[10];
    const float* b_gen = (const float*)d_in[11];
    float* out = (float*)d_out;

    prep_kernel<<<1024, 256>>>(W_feat, W_hid, W_ih, W_hh, b_ih, b_hh, W_gen);
    cast_bh_kernel<<<8192, 256>>>(batch_H);
    // feat: M=B*T=65536, N=512, K=512
    gemm_kernel<0><<<dim3(4, 1024), 256>>>(0, nullptr, nullptr, 0, 0, nullptr, nullptr);

    for (int s = 0; s < SS; s++) {
        int cur = s & 1, nxt = cur ^ 1;
        // hp = h @ W_hid^T + b_hid : M=512, N=512
        gemm_kernel<1><<<dim3(4, 8), 256>>>(cur, nullptr, b_hid, 0, 0, nullptr, nullptr);
        // attention (512 CTAs) overlapped with gh = h @ W_hh_p^T (128 CTAs)
        att_gh_kernel<<<BB + 128, 256>>>(cur, w_score);
        // gates = ctx @ W_ih_p^T (K=512) + gh + bias + onehot, LSTM pointwise
        gemm_kernel<2><<<dim3(16, 8), 256>>>(cur, nullptr, nullptr, s, nxt, W_ih, text);
    }
    // probs = out_h @ W_gen^T + b_gen : M=B*S=13312, N=97(pad 128)
    gemm_kernel<3><<<dim3(1, 208), 256>>>(0, out, b_gen, 0, 0, nullptr, nullptr);
}